// round 4
// baseline (speedup 1.0000x reference)
#include <cuda_runtime.h>

// ChannelExchangeWithConv: N=1, C=128, H=W=512, p=2
// out_lst = copy(lst); out_lst[::2] = W2 @ gui[::2] + b2
// out_gui = copy(gui); out_gui[::2] = W1 @ lst[::2] + b1

#define HW   262144
#define TP   256
#define NCTA (HW / TP)
#define CH   64
#define WROW 68      // padded row stride for Wt (16B-aligned, 4-way STS conflicts only)

typedef unsigned long long u64;

__device__ __forceinline__ u64 pkdup(float x) {
    u64 r; asm("mov.b64 %0, {%1, %1};" : "=l"(r) : "f"(x)); return r;
}
__device__ __forceinline__ u64 pk2(float x, float y) {
    u64 r; asm("mov.b64 %0, {%1, %2};" : "=l"(r) : "f"(x), "f"(y)); return r;
}
__device__ __forceinline__ void unpk(u64 v, float& lo, float& hi) {
    asm("mov.b64 {%0, %1}, %2;" : "=f"(lo), "=f"(hi) : "l"(v));
}
// packed 2-wide fp32 fma: acc += a*b (two independent fp32 lanes)
#define FMA2(acc, a, b) \
    asm("fma.rn.f32x2 %0, %1, %2, %0;" : "+l"(acc) : "l"(a), "l"(b))

__global__ __launch_bounds__(512, 2)
void cx_kernel(const float* __restrict__ lst, const float* __restrict__ gui,
               const float* __restrict__ w1,  const float* __restrict__ b1,
               const float* __restrict__ w2,  const float* __restrict__ b2,
               float* __restrict__ out)
{
    extern __shared__ float smem[];
    float* Xs = smem;                 // [64][256] conv-input tile (64 KB)
    float* Wt = smem + CH * TP;       // [64][68]  W transposed: Wt[c][o] = W[o][c]
    float* Bs = Wt + CH * WROW;       // [64] bias

    const int   dir  = blockIdx.y;                      // 0: out_lst, 1: out_gui
    const float* xin  = dir ? lst : gui;                // conv input (even channels)
    const float* cpin = dir ? gui : lst;                // passthrough src (odd channels)
    const float* W    = dir ? w1 : w2;
    const float* B    = dir ? b1 : b2;
    float* oo = out + (size_t)dir * 128 * HW;

    const int pix0 = blockIdx.x * TP;
    const int tid  = threadIdx.x;

    // --- weight transpose into smem: coalesced LDG, 4-way-conflict STS (8 instrs) ---
    #pragma unroll
    for (int i = 0; i < 8; i++) {
        int idx = i * 512 + tid;        // 0..4095
        int o = idx >> 6;
        int c = idx & 63;
        Wt[c * WROW + o] = W[o * CH + c];
    }
    if (tid < CH) Bs[tid] = B[tid];

    // --- stage even channels of xin into smem; stream odd-channel passthrough ---
    #pragma unroll
    for (int i = 0; i < 8; i++) {
        int idx = i * 512 + tid;        // float4 units over [64][64]
        int row = idx >> 6;             // masked-channel index 0..63
        int col = (idx & 63) << 2;      // float offset in tile
        float4 xv = *(const float4*)(xin + (size_t)(2 * row) * HW + pix0 + col);
        *(float4*)(Xs + row * TP + col) = xv;
        float4 cv = *(const float4*)(cpin + (size_t)(2 * row + 1) * HW + pix0 + col);
        *(float4*)(oo + (size_t)(2 * row + 1) * HW + pix0 + col) = cv;
    }
    __syncthreads();

    // --- GEMM: 16 warps = 2 px-groups x 8 o-groups. Warp tile 128px x 8o. ---
    // Thread tile: 4 px x 8 o, acc packed over o-pairs -> 16 f32x2 (32 regs).
    const int warp  = tid >> 5;
    const int q     = tid & 31;
    const int pxgrp = warp & 1;
    const int ogrp  = warp >> 1;             // 0..7
    const int px    = pxgrp * 128 + 4 * q;   // thread's 4 pixels
    const int obase = ogrp * 8;              // conv o in [obase, obase+8)

    u64 acc[4][4];
    #pragma unroll
    for (int j = 0; j < 4; j++) {
        u64 bb = pk2(Bs[obase + 2 * j], Bs[obase + 2 * j + 1]);
        acc[0][j] = bb; acc[1][j] = bb; acc[2][j] = bb; acc[3][j] = bb;
    }

    const float* xp = Xs + px;
    const float* wp = Wt + obase;

    #pragma unroll 4
    for (int c = 0; c < CH; c++) {
        float4 xv = *(const float4*)(xp + c * TP);          // 1 LDS.128 (distinct, 4 wf)
        u64 x0 = pkdup(xv.x), x1 = pkdup(xv.y), x2 = pkdup(xv.z), x3 = pkdup(xv.w);
        const u64* wr = (const u64*)(wp + c * WROW);        // consecutive o -> native pairs
        ulonglong2 wa = *(const ulonglong2*)(wr);           // {o0,o1},{o2,o3}  broadcast
        ulonglong2 wb = *(const ulonglong2*)(wr + 2);       // {o4,o5},{o6,o7}  broadcast
        u64 w[4] = {wa.x, wa.y, wb.x, wb.y};
        #pragma unroll
        for (int j = 0; j < 4; j++) {
            FMA2(acc[0][j], w[j], x0);
            FMA2(acc[1][j], w[j], x1);
            FMA2(acc[2][j], w[j], x2);
            FMA2(acc[3][j], w[j], x3);
        }
    }

    // --- store: pair j = conv o (obase+2j, obase+2j+1) -> global ch 2*obase+4j, +2 ---
    #pragma unroll
    for (int j = 0; j < 4; j++) {
        float a0, a1, b0v, b1v, c0, c1, d0, d1;
        unpk(acc[0][j], a0, a1);
        unpk(acc[1][j], b0v, b1v);
        unpk(acc[2][j], c0, c1);
        unpk(acc[3][j], d0, d1);
        size_t ch0 = (size_t)2 * obase + 4 * j;
        size_t ch1 = ch0 + 2;
        *(float4*)(oo + ch0 * HW + pix0 + px) = make_float4(a0, b0v, c0, d0);
        *(float4*)(oo + ch1 * HW + pix0 + px) = make_float4(a1, b1v, c1, d1);
    }
}

extern "C" void kernel_launch(void* const* d_in, const int* in_sizes, int n_in,
                              void* d_out, int out_size)
{
    const float* lst = (const float*)d_in[0];
    const float* gui = (const float*)d_in[1];
    const float* w1  = (const float*)d_in[2];
    const float* b1  = (const float*)d_in[3];
    const float* w2  = (const float*)d_in[4];
    const float* b2  = (const float*)d_in[5];
    float* out = (float*)d_out;

    const size_t smem = (size_t)CH * TP * 4 + (size_t)CH * WROW * 4 + CH * 4; // 83200 B
    cudaFuncSetAttribute(cx_kernel, cudaFuncAttributeMaxDynamicSharedMemorySize, (int)smem);

    dim3 grid(NCTA, 2);
    cx_kernel<<<grid, 512, smem>>>(lst, gui, w1, b1, w2, b2, out);
}

// round 6
// speedup vs baseline: 1.1078x; 1.1078x over previous
#include <cuda_runtime.h>
#include <cstdint>

// ChannelExchangeWithConv: N=1, C=128, H=W=512, p=2
// out_lst = copy(lst); out_lst[::2] = W2 @ gui[::2] + b2
// out_gui = copy(gui); out_gui[::2] = W1 @ lst[::2] + b1
// Persistent CTAs + cp.async double buffering to overlap DRAM with FMA.

#define HW    262144
#define TP    256
#define CH    64
#define WROW  68
#define NJOBS 2048        // 1024 tiles x 2 directions
#define NCTAS 148

typedef unsigned long long u64;

__device__ __forceinline__ u64 pkdup(float x) {
    u64 r; asm("mov.b64 %0, {%1, %1};" : "=l"(r) : "f"(x)); return r;
}
__device__ __forceinline__ u64 pk2(float x, float y) {
    u64 r; asm("mov.b64 %0, {%1, %2};" : "=l"(r) : "f"(x), "f"(y)); return r;
}
__device__ __forceinline__ void unpk(u64 v, float& lo, float& hi) {
    asm("mov.b64 {%0, %1}, %2;" : "=f"(lo), "=f"(hi) : "l"(v));
}
#define FMA2(acc, a, b) \
    asm("fma.rn.f32x2 %0, %1, %2, %0;" : "+l"(acc) : "l"(a), "l"(b))

__device__ __forceinline__ void cpasync16(uint32_t s, const void* g) {
    asm volatile("cp.async.cg.shared.global [%0], [%1], 16;" :: "r"(s), "l"(g));
}

__global__ __launch_bounds__(512, 1)
void cx_kernel(const float* __restrict__ lst, const float* __restrict__ gui,
               const float* __restrict__ w1,  const float* __restrict__ b1,
               const float* __restrict__ w2,  const float* __restrict__ b2,
               float* __restrict__ out)
{
    extern __shared__ float smem[];
    float* Xbuf = smem;                         // [2][64][256]  double-buffered x tiles
    float* Wt   = smem + 2 * CH * TP;           // [2][64][68]   dir0=w2t, dir1=w1t
    float* Bs   = Wt + 2 * CH * WROW;           // [2][64]

    const int tid = threadIdx.x;
    const int bx  = blockIdx.x;

    // --- stage BOTH weight sets (transposed) + biases, once per CTA ---
    #pragma unroll
    for (int i = 0; i < 16; i++) {
        int idx = i * 512 + tid;      // 0..8191
        int d   = idx >> 12;          // 0:dir0(w2) 1:dir1(w1)
        int o   = (idx >> 6) & 63;
        int c   = idx & 63;
        const float* W = d ? w1 : w2;
        Wt[(d * CH + c) * WROW + o] = W[o * CH + c];
    }
    if (tid < 2 * CH) Bs[tid] = (tid < CH) ? b2[tid] : b1[tid - CH];

    // per-thread tile-load mapping (8 float4 per thread over [64][64] float4 grid)
    const int lrow = tid >> 6;            // base row for i-th chunk: lrow + 8*i
    const int lcol = (tid & 63) << 2;

    const uint32_t sX0 = (uint32_t)__cvta_generic_to_shared(Xbuf);
    const uint32_t sX1 = (uint32_t)__cvta_generic_to_shared(Xbuf + CH * TP);

    // GEMM thread mapping: 16 warps = 2 px-groups x 8 o-groups; thread 4px x 8o
    const int warp  = tid >> 5;
    const int q     = tid & 31;
    const int px    = (warp & 1) * 128 + 4 * q;
    const int obase = (warp >> 1) * 8;

    // --- prologue: prefetch job0 x-tile into buf0 ---
    {
        int j = bx;
        int dir = j >> 10, tile = j & 1023;
        const float* xin = dir ? lst : gui;
        const float* gp  = xin + (size_t)tile * TP + lcol;
        #pragma unroll
        for (int i = 0; i < 8; i++) {
            int row = lrow + 8 * i;
            cpasync16(sX0 + (uint32_t)(row * TP + lcol) * 4, gp + (size_t)(2 * row) * HW);
        }
        asm volatile("cp.async.commit_group;");
    }

    int it = 0;
    for (int j = bx; j < NJOBS; j += NCTAS, it++) {
        const int cur = it & 1;
        const int dir = j >> 10, tile = j & 1023;
        const int pix0 = tile * TP;
        const float* cpin = dir ? gui : lst;
        float* oo = out + (size_t)dir * 128 * HW;

        // prefetch next job into other buffer, then wait for current
        const int jn = j + NCTAS;
        if (jn < NJOBS) {
            int dn = jn >> 10, tn = jn & 1023;
            const float* xinN = dn ? lst : gui;
            uint32_t sdst = cur ? sX0 : sX1;
            const float* gpN = xinN + (size_t)tn * TP + lcol;
            #pragma unroll
            for (int i = 0; i < 8; i++) {
                int row = lrow + 8 * i;
                cpasync16(sdst + (uint32_t)(row * TP + lcol) * 4, gpN + (size_t)(2 * row) * HW);
            }
            asm volatile("cp.async.commit_group;");
            asm volatile("cp.async.wait_group 1;");
        } else {
            asm volatile("cp.async.wait_group 0;");
        }
        __syncthreads();

        const float* Xs = Xbuf + cur * CH * TP;
        const float* Wd = Wt + dir * CH * WROW + obase;
        const float* Bd = Bs + dir * CH;

        // acc init with bias
        u64 acc[4][4];
        #pragma unroll
        for (int jj = 0; jj < 4; jj++) {
            u64 bb = pk2(Bd[obase + 2 * jj], Bd[obase + 2 * jj + 1]);
            acc[0][jj] = bb; acc[1][jj] = bb; acc[2][jj] = bb; acc[3][jj] = bb;
        }

        // copy batch A: issue LDGs now, hide behind first GEMM half
        float4 cpv[4];
        #pragma unroll
        for (int i = 0; i < 4; i++) {
            int idx = i * 512 + tid;
            int row = idx >> 6, col = (idx & 63) << 2;
            cpv[i] = *(const float4*)(cpin + (size_t)(2 * row + 1) * HW + pix0 + col);
        }

        const float* xp = Xs + px;

        // GEMM first half k = 0..31
        #pragma unroll 4
        for (int c = 0; c < 32; c++) {
            float4 xv = *(const float4*)(xp + c * TP);
            u64 x0 = pkdup(xv.x), x1 = pkdup(xv.y), x2 = pkdup(xv.z), x3 = pkdup(xv.w);
            const u64* wr = (const u64*)(Wd + c * WROW);
            ulonglong2 wa = *(const ulonglong2*)(wr);
            ulonglong2 wb = *(const ulonglong2*)(wr + 2);
            u64 w[4] = {wa.x, wa.y, wb.x, wb.y};
            #pragma unroll
            for (int jj = 0; jj < 4; jj++) {
                FMA2(acc[0][jj], w[jj], x0);
                FMA2(acc[1][jj], w[jj], x1);
                FMA2(acc[2][jj], w[jj], x2);
                FMA2(acc[3][jj], w[jj], x3);
            }
        }

        // drain batch A, issue batch B (hidden behind second GEMM half)
        #pragma unroll
        for (int i = 0; i < 4; i++) {
            int idx = i * 512 + tid;
            int row = idx >> 6, col = (idx & 63) << 2;
            *(float4*)(oo + (size_t)(2 * row + 1) * HW + pix0 + col) = cpv[i];
        }
        #pragma unroll
        for (int i = 0; i < 4; i++) {
            int idx = (i + 4) * 512 + tid;
            int row = idx >> 6, col = (idx & 63) << 2;
            cpv[i] = *(const float4*)(cpin + (size_t)(2 * row + 1) * HW + pix0 + col);
        }

        // GEMM second half k = 32..63
        #pragma unroll 4
        for (int c = 32; c < CH; c++) {
            float4 xv = *(const float4*)(xp + c * TP);
            u64 x0 = pkdup(xv.x), x1 = pkdup(xv.y), x2 = pkdup(xv.z), x3 = pkdup(xv.w);
            const u64* wr = (const u64*)(Wd + c * WROW);
            ulonglong2 wa = *(const ulonglong2*)(wr);
            ulonglong2 wb = *(const ulonglong2*)(wr + 2);
            u64 w[4] = {wa.x, wa.y, wb.x, wb.y};
            #pragma unroll
            for (int jj = 0; jj < 4; jj++) {
                FMA2(acc[0][jj], w[jj], x0);
                FMA2(acc[1][jj], w[jj], x1);
                FMA2(acc[2][jj], w[jj], x2);
                FMA2(acc[3][jj], w[jj], x3);
            }
        }

        // drain batch B
        #pragma unroll
        for (int i = 0; i < 4; i++) {
            int idx = (i + 4) * 512 + tid;
            int row = idx >> 6, col = (idx & 63) << 2;
            *(float4*)(oo + (size_t)(2 * row + 1) * HW + pix0 + col) = cpv[i];
        }

        // store GEMM outputs: pair jj = conv o (obase+2jj, +1) -> global ch 2*obase+4jj, +2
        #pragma unroll
        for (int jj = 0; jj < 4; jj++) {
            float a0, a1, b0v, b1v, c0, c1, d0, d1;
            unpk(acc[0][jj], a0, a1);
            unpk(acc[1][jj], b0v, b1v);
            unpk(acc[2][jj], c0, c1);
            unpk(acc[3][jj], d0, d1);
            size_t ch0 = (size_t)2 * obase + 4 * jj;
            *(float4*)(oo + ch0 * HW + pix0 + px)       = make_float4(a0, b0v, c0, d0);
            *(float4*)(oo + (ch0 + 2) * HW + pix0 + px) = make_float4(a1, b1v, c1, d1);
        }

        __syncthreads();   // all reads of buf[cur] done before it is refilled next iter
    }
}

extern "C" void kernel_launch(void* const* d_in, const int* in_sizes, int n_in,
                              void* d_out, int out_size)
{
    const float* lst = (const float*)d_in[0];
    const float* gui = (const float*)d_in[1];
    const float* w1  = (const float*)d_in[2];
    const float* b1  = (const float*)d_in[3];
    const float* w2  = (const float*)d_in[4];
    const float* b2  = (const float*)d_in[5];
    float* out = (float*)d_out;

    const size_t smem = (size_t)2 * CH * TP * 4 + (size_t)2 * CH * WROW * 4 + 2 * CH * 4; // 166400
    cudaFuncSetAttribute(cx_kernel, cudaFuncAttributeMaxDynamicSharedMemorySize, (int)smem);

    cx_kernel<<<NCTAS, 512, smem>>>(lst, gui, w1, b1, w2, b2, out);
}

// round 7
// speedup vs baseline: 1.1406x; 1.0296x over previous
#include <cuda_runtime.h>
#include <cstdint>

// ChannelExchangeWithConv: N=1, C=128, H=W=512, p=2
// Persistent CTAs (2 per SM, independent barrier domains) + cp.async double buffering.

#define HW    262144
#define TP    128
#define CH    64
#define WROW  68
#define NT    (HW / TP)       // 2048 tiles per direction
#define NJOBS (2 * NT)        // 4096
#define NCTAS 296             // 2 per SM

typedef unsigned long long u64;

__device__ __forceinline__ u64 pkdup(float x) {
    u64 r; asm("mov.b64 %0, {%1, %1};" : "=l"(r) : "f"(x)); return r;
}
__device__ __forceinline__ u64 pk2(float x, float y) {
    u64 r; asm("mov.b64 %0, {%1, %2};" : "=l"(r) : "f"(x), "f"(y)); return r;
}
__device__ __forceinline__ void unpk(u64 v, float& lo, float& hi) {
    asm("mov.b64 {%0, %1}, %2;" : "=f"(lo), "=f"(hi) : "l"(v));
}
#define FMA2(acc, a, b) \
    asm("fma.rn.f32x2 %0, %1, %2, %0;" : "+l"(acc) : "l"(a), "l"(b))

__device__ __forceinline__ void cpasync16(uint32_t s, const void* g) {
    asm volatile("cp.async.cg.shared.global [%0], [%1], 16;" :: "r"(s), "l"(g));
}

__global__ __launch_bounds__(256, 2)
void cx_kernel(const float* __restrict__ lst, const float* __restrict__ gui,
               const float* __restrict__ w1,  const float* __restrict__ b1,
               const float* __restrict__ w2,  const float* __restrict__ b2,
               float* __restrict__ out)
{
    extern __shared__ float smem[];
    float* Xbuf = smem;                         // [2][64][128] double-buffered x tiles (64 KB)
    float* Wt   = smem + 2 * CH * TP;           // [2][64][68]  dir0=w2t, dir1=w1t (34 KB)
    float* Bs   = Wt + 2 * CH * WROW;           // [2][64]

    const int tid = threadIdx.x;
    const int bx  = blockIdx.x;

    // --- stage BOTH weight sets (transposed) + biases, once per CTA ---
    #pragma unroll
    for (int i = 0; i < 32; i++) {
        int idx = i * 256 + tid;      // 0..8191
        int d   = idx >> 12;
        int o   = (idx >> 6) & 63;
        int c   = idx & 63;
        const float* W = d ? w1 : w2;
        Wt[(d * CH + c) * WROW + o] = W[o * CH + c];
    }
    if (tid < 2 * CH) Bs[tid] = (tid < CH) ? b2[tid] : b1[tid - CH];

    // x-tile cp.async mapping: [64 rows][32 float4 cols], 8 float4 per thread
    const int lrow = tid >> 5;            // base row for chunk i: lrow + 8*i
    const int lcol = (tid & 31) << 2;

    const uint32_t sX0 = (uint32_t)__cvta_generic_to_shared(Xbuf);
    const uint32_t sX1 = (uint32_t)__cvta_generic_to_shared(Xbuf + CH * TP);

    // GEMM mapping: 8 warps = 8 o-groups; thread tile 4px x 8o
    const int warp  = tid >> 5;
    const int q     = tid & 31;
    const int px    = 4 * q;              // 0..124
    const int obase = warp * 8;

    // --- prologue: prefetch job0 x-tile into buf0 ---
    {
        int j = bx;
        int dir = j >> 11, tile = j & (NT - 1);
        const float* xin = dir ? lst : gui;
        const float* gp  = xin + (size_t)tile * TP + lcol;
        #pragma unroll
        for (int i = 0; i < 8; i++) {
            int row = lrow + 8 * i;
            cpasync16(sX0 + (uint32_t)(row * TP + lcol) * 4, gp + (size_t)(2 * row) * HW);
        }
        asm volatile("cp.async.commit_group;");
    }

    int it = 0;
    for (int j = bx; j < NJOBS; j += NCTAS, it++) {
        const int cur = it & 1;
        const int dir = j >> 11, tile = j & (NT - 1);
        const int pix0 = tile * TP;
        const float* cpin = dir ? gui : lst;
        float* oo = out + (size_t)dir * 128 * HW;

        // prefetch next job into other buffer, then wait for current
        const int jn = j + NCTAS;
        if (jn < NJOBS) {
            int dn = jn >> 11, tn = jn & (NT - 1);
            const float* xinN = dn ? lst : gui;
            uint32_t sdst = cur ? sX0 : sX1;
            const float* gpN = xinN + (size_t)tn * TP + lcol;
            #pragma unroll
            for (int i = 0; i < 8; i++) {
                int row = lrow + 8 * i;
                cpasync16(sdst + (uint32_t)(row * TP + lcol) * 4, gpN + (size_t)(2 * row) * HW);
            }
            asm volatile("cp.async.commit_group;");
            asm volatile("cp.async.wait_group 1;");
        } else {
            asm volatile("cp.async.wait_group 0;");
        }
        __syncthreads();

        const float* Xs = Xbuf + cur * CH * TP;
        const float* Wd = Wt + dir * CH * WROW + obase;
        const float* Bd = Bs + dir * CH;

        // acc init with bias
        u64 acc[4][4];
        #pragma unroll
        for (int jj = 0; jj < 4; jj++) {
            u64 bb = pk2(Bd[obase + 2 * jj], Bd[obase + 2 * jj + 1]);
            acc[0][jj] = bb; acc[1][jj] = bb; acc[2][jj] = bb; acc[3][jj] = bb;
        }

        // copy batch A (rows 0..31): issue LDGs, hide behind first GEMM half
        float4 cpv[4];
        #pragma unroll
        for (int i = 0; i < 4; i++) {
            int idx = i * 256 + tid;
            int row = idx >> 5, col = (idx & 31) << 2;
            cpv[i] = *(const float4*)(cpin + (size_t)(2 * row + 1) * HW + pix0 + col);
        }

        const float* xp = Xs + px;

        // GEMM first half k = 0..31
        #pragma unroll 4
        for (int c = 0; c < 32; c++) {
            float4 xv = *(const float4*)(xp + c * TP);
            u64 x0 = pkdup(xv.x), x1 = pkdup(xv.y), x2 = pkdup(xv.z), x3 = pkdup(xv.w);
            const u64* wr = (const u64*)(Wd + c * WROW);
            ulonglong2 wa = *(const ulonglong2*)(wr);
            ulonglong2 wb = *(const ulonglong2*)(wr + 2);
            u64 w[4] = {wa.x, wa.y, wb.x, wb.y};
            #pragma unroll
            for (int jj = 0; jj < 4; jj++) {
                FMA2(acc[0][jj], w[jj], x0);
                FMA2(acc[1][jj], w[jj], x1);
                FMA2(acc[2][jj], w[jj], x2);
                FMA2(acc[3][jj], w[jj], x3);
            }
        }

        // drain batch A, issue batch B (rows 32..63)
        #pragma unroll
        for (int i = 0; i < 4; i++) {
            int idx = i * 256 + tid;
            int row = idx >> 5, col = (idx & 31) << 2;
            *(float4*)(oo + (size_t)(2 * row + 1) * HW + pix0 + col) = cpv[i];
        }
        #pragma unroll
        for (int i = 0; i < 4; i++) {
            int idx = (i + 4) * 256 + tid;
            int row = idx >> 5, col = (idx & 31) << 2;
            cpv[i] = *(const float4*)(cpin + (size_t)(2 * row + 1) * HW + pix0 + col);
        }

        // GEMM second half k = 32..63
        #pragma unroll 4
        for (int c = 32; c < CH; c++) {
            float4 xv = *(const float4*)(xp + c * TP);
            u64 x0 = pkdup(xv.x), x1 = pkdup(xv.y), x2 = pkdup(xv.z), x3 = pkdup(xv.w);
            const u64* wr = (const u64*)(Wd + c * WROW);
            ulonglong2 wa = *(const ulonglong2*)(wr);
            ulonglong2 wb = *(const ulonglong2*)(wr + 2);
            u64 w[4] = {wa.x, wa.y, wb.x, wb.y};
            #pragma unroll
            for (int jj = 0; jj < 4; jj++) {
                FMA2(acc[0][jj], w[jj], x0);
                FMA2(acc[1][jj], w[jj], x1);
                FMA2(acc[2][jj], w[jj], x2);
                FMA2(acc[3][jj], w[jj], x3);
            }
        }

        // drain batch B
        #pragma unroll
        for (int i = 0; i < 4; i++) {
            int idx = (i + 4) * 256 + tid;
            int row = idx >> 5, col = (idx & 31) << 2;
            *(float4*)(oo + (size_t)(2 * row + 1) * HW + pix0 + col) = cpv[i];
        }

        // store GEMM outputs: pair jj = conv o (obase+2jj, +1) -> global ch 2*obase+4jj, +2
        #pragma unroll
        for (int jj = 0; jj < 4; jj++) {
            float a0, a1, b0v, b1v, c0, c1, d0, d1;
            unpk(acc[0][jj], a0, a1);
            unpk(acc[1][jj], b0v, b1v);
            unpk(acc[2][jj], c0, c1);
            unpk(acc[3][jj], d0, d1);
            size_t ch0 = (size_t)2 * obase + 4 * jj;
            *(float4*)(oo + ch0 * HW + pix0 + px)       = make_float4(a0, b0v, c0, d0);
            *(float4*)(oo + (ch0 + 2) * HW + pix0 + px) = make_float4(a1, b1v, c1, d1);
        }

        __syncthreads();   // all reads of buf[cur] done before it is refilled next iter
    }
}

extern "C" void kernel_launch(void* const* d_in, const int* in_sizes, int n_in,
                              void* d_out, int out_size)
{
    const float* lst = (const float*)d_in[0];
    const float* gui = (const float*)d_in[1];
    const float* w1  = (const float*)d_in[2];
    const float* b1  = (const float*)d_in[3];
    const float* w2  = (const float*)d_in[4];
    const float* b2  = (const float*)d_in[5];
    float* out = (float*)d_out;

    const size_t smem = (size_t)2 * CH * TP * 4 + (size_t)2 * CH * WROW * 4 + 2 * CH * 4; // 100864 B
    cudaFuncSetAttribute(cx_kernel, cudaFuncAttributeMaxDynamicSharedMemorySize, (int)smem);

    cx_kernel<<<NCTAS, 256, smem>>>(lst, gui, w1, b1, w2, b2, out);
}